// round 11
// baseline (speedup 1.0000x reference)
#include <cuda_runtime.h>
#include <cuda_bf16.h>
#include <math.h>
#include <float.h>
#include <stdlib.h>

// ---------------------------------------------------------------------------
// snn_test: B=64, T=256, F=1024, H=512 — bf16 MMA v4
//   prep:   split f_f, W2, Mw1 into bf16 hi/lo
//   wc:     Wc = W1 @ Wf (fp32, 1024 thr, 4-way in-block split-K) -> hi/lo
//   fused1: x1 = f_f @ Wc^T + bc (3-pass split bf16) -> scan -> s1 bits
//           [1 block-sync per 16-k chunk; warp-local A staging]
//   fused2: x2 = s1 @ W2^T + b2 (2-pass) -> scan -> s2 bits  [32-k chunks]
//   fusedM: relu(s2 @ Mw1^T + Mb1) . v (2-pass) -> logit partials
//   topk:   sigmoid + top-17 mean
// Launch order puts fused1 at index 3 so ncu's fixed skip captures it.
// ---------------------------------------------------------------------------

constexpr int Bb   = 64;
constexpr int Tt   = 256;
constexpr int Fdim = 1024;
constexpr int Hdim = 512;
constexpr int BT   = Bb * Tt;
constexpr int TOPK = Tt / 16 + 1;      // 17
constexpr int WPR  = Hdim / 32;        // 16
constexpr int FF_N = Bb * Tt * Fdim;   // 16,777,216
constexpr int WW_N = Hdim * Hdim;      // 262,144

// ---- device-global scratch (~41 MB) ----
__device__ __nv_bfloat16 g_ffH[FF_N];
__device__ __nv_bfloat16 g_ffL[FF_N];
__device__ __nv_bfloat16 g_WcH[Hdim * Fdim];
__device__ __nv_bfloat16 g_WcL[Hdim * Fdim];
__device__ __nv_bfloat16 g_W2H[WW_N];
__device__ __nv_bfloat16 g_W2L[WW_N];
__device__ __nv_bfloat16 g_M1H[WW_N];
__device__ __nv_bfloat16 g_M1L[WW_N];
__device__ float    g_bc[Hdim];
__device__ float    g_v[Hdim];
__device__ float    g_cbias;
__device__ unsigned g_s1bits[BT * WPR];
__device__ unsigned g_s2bits[BT * WPR];
__device__ float    g_logitParts[8 * BT];

// ---------------------------------------------------------------------------
// PTX helpers
// ---------------------------------------------------------------------------
__device__ __forceinline__ unsigned smem_u32(const void* p) {
    return (unsigned)__cvta_generic_to_shared(p);
}
__device__ __forceinline__ void ldm4(unsigned& r0, unsigned& r1, unsigned& r2, unsigned& r3,
                                     unsigned addr) {
    asm volatile("ldmatrix.sync.aligned.m8n8.x4.shared.b16 {%0,%1,%2,%3},[%4];"
                 : "=r"(r0), "=r"(r1), "=r"(r2), "=r"(r3) : "r"(addr));
}
__device__ __forceinline__ void mma16816(float* c, unsigned a0, unsigned a1, unsigned a2,
                                         unsigned a3, unsigned b0, unsigned b1) {
    asm volatile(
        "mma.sync.aligned.m16n8k16.row.col.f32.bf16.bf16.f32 "
        "{%0,%1,%2,%3},{%4,%5,%6,%7},{%8,%9},{%0,%1,%2,%3};"
        : "+f"(c[0]), "+f"(c[1]), "+f"(c[2]), "+f"(c[3])
        : "r"(a0), "r"(a1), "r"(a2), "r"(a3), "r"(b0), "r"(b1));
}
__device__ __forceinline__ void cp_async16(void* sdst, const void* gsrc) {
    asm volatile("cp.async.ca.shared.global [%0],[%1],16;"
                 :: "r"(smem_u32(sdst)), "l"(gsrc));
}
#define CP_COMMIT() asm volatile("cp.async.commit_group;")
#define CP_WAIT0()  asm volatile("cp.async.wait_group 0;")

// ---------------------------------------------------------------------------
// prep: hi/lo split of f_f, W2, Mw1
// ---------------------------------------------------------------------------
__device__ __forceinline__ void split4(float4 v, uint2& H, uint2& L) {
    __nv_bfloat16 h0 = __float2bfloat16_rn(v.x), h1 = __float2bfloat16_rn(v.y);
    __nv_bfloat16 h2 = __float2bfloat16_rn(v.z), h3 = __float2bfloat16_rn(v.w);
    __nv_bfloat16 l0 = __float2bfloat16_rn(v.x - __bfloat162float(h0));
    __nv_bfloat16 l1 = __float2bfloat16_rn(v.y - __bfloat162float(h1));
    __nv_bfloat16 l2 = __float2bfloat16_rn(v.z - __bfloat162float(h2));
    __nv_bfloat16 l3 = __float2bfloat16_rn(v.w - __bfloat162float(h3));
    H.x = ((unsigned)__bfloat16_as_ushort(h1) << 16) | __bfloat16_as_ushort(h0);
    H.y = ((unsigned)__bfloat16_as_ushort(h3) << 16) | __bfloat16_as_ushort(h2);
    L.x = ((unsigned)__bfloat16_as_ushort(l1) << 16) | __bfloat16_as_ushort(l0);
    L.y = ((unsigned)__bfloat16_as_ushort(l3) << 16) | __bfloat16_as_ushort(l2);
}

__global__ void prep_split_kernel(const float* __restrict__ f_f,
                                  const float* __restrict__ W2,
                                  const float* __restrict__ Mw1) {
    const int FF4 = FF_N / 4, WW4 = WW_N / 4;
    int i = blockIdx.x * 256 + threadIdx.x;
    uint2 H, L;
    if (i < FF4) {
        split4(reinterpret_cast<const float4*>(f_f)[i], H, L);
        reinterpret_cast<uint2*>(g_ffH)[i] = H;
        reinterpret_cast<uint2*>(g_ffL)[i] = L;
    } else if (i < FF4 + WW4) {
        int j = i - FF4;
        split4(reinterpret_cast<const float4*>(W2)[j], H, L);
        reinterpret_cast<uint2*>(g_W2H)[j] = H;
        reinterpret_cast<uint2*>(g_W2L)[j] = L;
    } else {
        int j = i - FF4 - WW4;
        split4(reinterpret_cast<const float4*>(Mw1)[j], H, L);
        reinterpret_cast<uint2*>(g_M1H)[j] = H;
        reinterpret_cast<uint2*>(g_M1L)[j] = L;
    }
}

// ---------------------------------------------------------------------------
// bc[n] = W1[n,:]·bf + b1[n]
// ---------------------------------------------------------------------------
__global__ void bc_kernel(const float* __restrict__ W1, const float* __restrict__ bf,
                          const float* __restrict__ b1) {
    __shared__ float red[128];
    int n = blockIdx.x;
    float s = 0.f;
    for (int j = threadIdx.x; j < Hdim; j += 128)
        s = fmaf(W1[n * Hdim + j], bf[j], s);
    red[threadIdx.x] = s;
    __syncthreads();
    for (int st = 64; st > 0; st >>= 1) {
        if (threadIdx.x < st) red[threadIdx.x] += red[threadIdx.x + st];
        __syncthreads();
    }
    if (threadIdx.x == 0) g_bc[n] = red[0] + b1[n];
}

// ---------------------------------------------------------------------------
// v[j] = Mw3 · Mw2[:,j];  cbias = Mw3·Mb2 + Mb3
// ---------------------------------------------------------------------------
__global__ void vc_kernel(const float* __restrict__ Mw2, const float* __restrict__ Mb2,
                          const float* __restrict__ Mw3, const float* __restrict__ Mb3) {
    int j = blockIdx.x * blockDim.x + threadIdx.x;
    if (j < Hdim) {
        float s = 0.f;
        #pragma unroll
        for (int k = 0; k < 32; k++) s = fmaf(Mw3[k], Mw2[k * Hdim + j], s);
        g_v[j] = s;
    }
    if (j == 0) {
        float c = Mb3[0];
        #pragma unroll
        for (int k = 0; k < 32; k++) c = fmaf(Mw3[k], Mb2[k], c);
        g_cbias = c;
    }
}

// ---------------------------------------------------------------------------
// Wc = W1 @ Wf (fp32, 64x64 tile, 1024 thr, 4-way in-block split-K).
// Epilogue writes hi/lo bf16. Deterministic reduce order.
// ---------------------------------------------------------------------------
__global__ __launch_bounds__(1024) void wc_kernel(const float* __restrict__ W1,
                                                  const float* __restrict__ Wf) {
    __shared__ float sm[8704];   // 4 groups x (As 1088 + Bs 1088) floats
    const int tid = threadIdx.x;
    const int g = tid >> 8;
    const int t = tid & 255;
    const int tym = t >> 4, txn = t & 15;
    const int m0 = blockIdx.y * 64, n0 = blockIdx.x * 64;
    float* Asg = sm + g * 2176;           // [16][68]
    float* Bsg = Asg + 1088;              // [16][68]
    float acc[4][4];
    #pragma unroll
    for (int i = 0; i < 4; i++)
        #pragma unroll
        for (int j = 0; j < 4; j++) acc[i][j] = 0.f;

    const int kbase = g * 128;
    for (int kt = 0; kt < 128; kt += 16) {
        const int k = kbase + kt;
        {
            int r = t >> 2, c = (t & 3) * 4;
            const float4 v = *reinterpret_cast<const float4*>(W1 + (size_t)(m0 + r) * Hdim + k + c);
            Asg[(c + 0) * 68 + r] = v.x; Asg[(c + 1) * 68 + r] = v.y;
            Asg[(c + 2) * 68 + r] = v.z; Asg[(c + 3) * 68 + r] = v.w;
        }
        {
            int kr = t >> 4, cc = (t & 15) * 4;
            const float4 v = *reinterpret_cast<const float4*>(Wf + (size_t)(k + kr) * Fdim + n0 + cc);
            *reinterpret_cast<float4*>(&Bsg[kr * 68 + cc]) = v;
        }
        __syncthreads();
        #pragma unroll
        for (int kk = 0; kk < 16; kk++) {
            float a[4], b[4];
            #pragma unroll
            for (int i = 0; i < 4; i++) a[i] = Asg[kk * 68 + tym * 4 + i];
            #pragma unroll
            for (int j = 0; j < 4; j++) b[j] = Bsg[kk * 68 + txn * 4 + j];
            #pragma unroll
            for (int i = 0; i < 4; i++)
                #pragma unroll
                for (int j = 0; j < 4; j++)
                    acc[i][j] = fmaf(a[i], b[j], acc[i][j]);
        }
        __syncthreads();
    }
    // tree reduce: part0 = sm[0..4352), part1 = sm[4352..8704) as [64][68]
    float* part0 = sm;
    float* part1 = sm + 4352;
    __syncthreads();
    if (g == 1 || g == 3) {
        float* p = (g == 1) ? part0 : part1;
        #pragma unroll
        for (int i = 0; i < 4; i++)
            #pragma unroll
            for (int j = 0; j < 4; j++)
                p[(tym * 4 + i) * 68 + txn * 4 + j] = acc[i][j];
    }
    __syncthreads();
    if (g == 0)
        #pragma unroll
        for (int i = 0; i < 4; i++)
            #pragma unroll
            for (int j = 0; j < 4; j++)
                acc[i][j] += part0[(tym * 4 + i) * 68 + txn * 4 + j];
    if (g == 2)
        #pragma unroll
        for (int i = 0; i < 4; i++)
            #pragma unroll
            for (int j = 0; j < 4; j++)
                acc[i][j] += part1[(tym * 4 + i) * 68 + txn * 4 + j];
    __syncthreads();
    if (g == 2) {
        #pragma unroll
        for (int i = 0; i < 4; i++)
            #pragma unroll
            for (int j = 0; j < 4; j++)
                part0[(tym * 4 + i) * 68 + txn * 4 + j] = acc[i][j];
    }
    __syncthreads();
    if (g == 0) {
        #pragma unroll
        for (int i = 0; i < 4; i++)
            #pragma unroll
            for (int j = 0; j < 4; j++) {
                float v = acc[i][j] + part0[(tym * 4 + i) * 68 + txn * 4 + j];
                size_t off = (size_t)(m0 + tym * 4 + i) * Fdim + n0 + txn * 4 + j;
                __nv_bfloat16 h = __float2bfloat16_rn(v);
                g_WcH[off] = h;
                g_WcL[off] = __float2bfloat16_rn(v - __bfloat162float(h));
            }
    }
}

// ---------------------------------------------------------------------------
// Fragment scan + bit-pack (top sync guards xs-over-A aliasing)
// ---------------------------------------------------------------------------
__device__ __forceinline__ void scan_frags_and_pack(
    float (&acc)[2][8][4], float (*xs)[68],
    int b, int n0, unsigned* __restrict__ bits_out)
{
    const int tid = threadIdx.x;
    const int w = tid >> 5, lane = tid & 31;
    const int q = lane >> 2, cp = 2 * (lane & 3);
    float m = 0.f;
    __syncthreads();   // all warps past final ldmatrix before xs overwrites A
    #pragma unroll
    for (int c = 0; c < 4; c++) {
        if ((w >> 1) == c) {
            const int rb = (w & 1) * 32;
            #pragma unroll
            for (int st = 0; st < 2; st++) {
                #pragma unroll
                for (int ns = 0; ns < 8; ns++) {
                    int r = rb + st * 16 + q;
                    int col = ns * 8 + cp;
                    xs[r][col]         = acc[st][ns][0];
                    xs[r][col + 1]     = acc[st][ns][1];
                    xs[r + 8][col]     = acc[st][ns][2];
                    xs[r + 8][col + 1] = acc[st][ns][3];
                }
            }
        }
        __syncthreads();
        if (w < 2) {
            for (int tt = 0; tt < 64; tt++) {
                float x = xs[tt][w * 32 + lane];
                float r = (m > 1.0f) ? 1.0f : 0.0f;
                m = 0.9f * m + x - r;
                unsigned bits = __ballot_sync(0xffffffffu, m > 1.0f);
                if (lane == 0)
                    bits_out[(size_t)(b * Tt + c * 64 + tt) * WPR + (n0 >> 5) + w] = bits;
            }
        }
        __syncthreads();
    }
}

// ---------------------------------------------------------------------------
// fused1: x1 = f_f[b] @ Wc^T + bc (3-pass), scan -> s1 bits.
// 16-k chunks; warp-local A staging; ONE block sync per chunk (B buffer swap).
// ---------------------------------------------------------------------------
__global__ __launch_bounds__(256, 2) void fused_x1_mma() {
    __shared__ __align__(16) char sbuf[36864];
    unsigned short (*AsH)[24] = reinterpret_cast<unsigned short(*)[24]>(sbuf);
    unsigned short (*AsL)[24] = reinterpret_cast<unsigned short(*)[24]>(sbuf + 12288);
    unsigned short (*BsH)[24] = reinterpret_cast<unsigned short(*)[24]>(sbuf + 24576);
    unsigned short (*BsL)[24] = reinterpret_cast<unsigned short(*)[24]>(sbuf + 30720);
    float (*xs)[68] = reinterpret_cast<float(*)[68]>(sbuf);

    const int tid = threadIdx.x;
    const int w = tid >> 5, lane = tid & 31;
    const int n0 = blockIdx.x * 64;
    const int b  = blockIdx.y;

    float acc[2][8][4];
    #pragma unroll
    for (int st = 0; st < 2; st++)
        #pragma unroll
        for (int ns = 0; ns < 8; ns++)
            #pragma unroll
            for (int i = 0; i < 4; i++) acc[st][ns][i] = 0.f;

    const int brow = (tid & 127) >> 1, bseg = tid & 1;
    const __nv_bfloat16* gsrcB = ((tid < 128) ? g_WcH : g_WcL)
                                 + (size_t)(n0 + brow) * Fdim + bseg * 8;
    unsigned short (*Bdst)[24] = (tid < 128) ? BsH : BsL;

    const __nv_bfloat16* aH = g_ffH + (size_t)(b * Tt + tid) * Fdim;
    const __nv_bfloat16* aL = g_ffL + (size_t)(b * Tt + tid) * Fdim;

    // preload B(0) + A(0) regs
    cp_async16(&Bdst[brow][bseg * 8], gsrcB);
    CP_COMMIT();
    uint4 rAH[2], rAL[2];
    rAH[0] = reinterpret_cast<const uint4*>(aH)[0];
    rAH[1] = reinterpret_cast<const uint4*>(aH)[1];
    rAL[0] = reinterpret_cast<const uint4*>(aL)[0];
    rAL[1] = reinterpret_cast<const uint4*>(aL)[1];

    const unsigned aRowBase = w * 32 + (lane & 15);
    const unsigned aKofs = (lane >> 4) * 16;
    const unsigned bRow = (lane & 7) + ((lane >> 4) & 1) * 8;
    const unsigned bKofs = ((lane >> 3) & 1) * 16;

    for (int c = 0; c < Fdim / 16; c++) {
        const int buf = c & 1;
        // warp-local A staging for chunk c
        *reinterpret_cast<uint4*>(&AsH[tid][0]) = rAH[0];
        *reinterpret_cast<uint4*>(&AsH[tid][8]) = rAH[1];
        *reinterpret_cast<uint4*>(&AsL[tid][0]) = rAL[0];
        *reinterpret_cast<uint4*>(&AsL[tid][8]) = rAL[1];
        if (c + 1 < Fdim / 16) {
            const int kt = (c + 1) * 16;
            rAH[0] = *reinterpret_cast<const uint4*>(aH + kt);
            rAH[1] = *reinterpret_cast<const uint4*>(aH + kt + 8);
            rAL[0] = *reinterpret_cast<const uint4*>(aL + kt);
            rAL[1] = *reinterpret_cast<const uint4*>(aL + kt + 8);
        }
        CP_WAIT0();            // B(c) arrived
        __syncthreads();       // all warps done reading B(c-1); B(c) visible
        if (c + 1 < Fdim / 16) {
            cp_async16(&Bdst[(buf ^ 1) * 64 + brow][bseg * 8], gsrcB + (c + 1) * 16);
            CP_COMMIT();
        }
        __syncwarp();          // A STS visible within warp

        unsigned ah[2][4], al[2][4];
        #pragma unroll
        for (int st = 0; st < 2; st++) {
            ldm4(ah[st][0], ah[st][1], ah[st][2], ah[st][3],
                 smem_u32(&AsH[aRowBase + st * 16][0]) + aKofs);
            ldm4(al[st][0], al[st][1], al[st][2], al[st][3],
                 smem_u32(&AsL[aRowBase + st * 16][0]) + aKofs);
        }
        #pragma unroll
        for (int p = 0; p < 4; p++) {
            unsigned bh[4], bl[4];
            ldm4(bh[0], bh[1], bh[2], bh[3],
                 smem_u32(&BsH[buf * 64 + p * 16 + bRow][0]) + bKofs);
            ldm4(bl[0], bl[1], bl[2], bl[3],
                 smem_u32(&BsL[buf * 64 + p * 16 + bRow][0]) + bKofs);
            #pragma unroll
            for (int st = 0; st < 2; st++) {
                mma16816(acc[st][2 * p], ah[st][0], ah[st][1], ah[st][2], ah[st][3], bh[0], bh[1]);
                mma16816(acc[st][2 * p], ah[st][0], ah[st][1], ah[st][2], ah[st][3], bl[0], bl[1]);
                mma16816(acc[st][2 * p], al[st][0], al[st][1], al[st][2], al[st][3], bh[0], bh[1]);
                mma16816(acc[st][2 * p + 1], ah[st][0], ah[st][1], ah[st][2], ah[st][3], bh[2], bh[3]);
                mma16816(acc[st][2 * p + 1], ah[st][0], ah[st][1], ah[st][2], ah[st][3], bl[2], bl[3]);
                mma16816(acc[st][2 * p + 1], al[st][0], al[st][1], al[st][2], al[st][3], bh[2], bh[3]);
            }
        }
        // no end-of-chunk sync: A is warp-local; B swap guarded by next top sync
    }
    {
        const int cp = 2 * (lane & 3);
        #pragma unroll
        for (int ns = 0; ns < 8; ns++) {
            float b0 = g_bc[n0 + ns * 8 + cp];
            float b1 = g_bc[n0 + ns * 8 + cp + 1];
            #pragma unroll
            for (int st = 0; st < 2; st++) {
                acc[st][ns][0] += b0; acc[st][ns][1] += b1;
                acc[st][ns][2] += b0; acc[st][ns][3] += b1;
            }
        }
    }
    scan_frags_and_pack(acc, xs, b, n0, g_s1bits);
}

// ---------------------------------------------------------------------------
// Shared body for fused2 / fusedM: A from spike bits, 32-k chunks, 2-pass B.
// smem: AsH[2ksub][256][24] @0 (24KB), BsH[2buf][2ksub][64][24] @24576 (12KB),
//       BsL @36864 (12KB). Total 48KB. ONE block sync per chunk.
// ---------------------------------------------------------------------------
__device__ __forceinline__ void spike_gemm_body(
    char* sbuf, const unsigned* __restrict__ bitsIn,
    const __nv_bfloat16* __restrict__ WH, const __nv_bfloat16* __restrict__ WL,
    int b, int n0, float (&acc)[2][8][4])
{
    const int tid = threadIdx.x;
    const int w = tid >> 5, lane = tid & 31;

    // B cp.async mapping: 2 units of 16B per thread
    // u = tid*2+j : hl = u>>8; r = u&255; ksub = r>>7; rr = r&127; row = rr>>1; seg = rr&1
    unsigned bDstOff[2];
    const __nv_bfloat16* bSrc[2];
    #pragma unroll
    for (int j = 0; j < 2; j++) {
        int u = tid * 2 + j;
        int hl = u >> 8, r = u & 255;
        int ksub = r >> 7, rr = r & 127;
        int row = rr >> 1, seg = rr & 1;
        bDstOff[j] = 24576 + hl * 12288 + ksub * 3072 + row * 48 + seg * 16;
        bSrc[j] = (hl ? WL : WH) + (size_t)(n0 + row) * Hdim + ksub * 16 + seg * 8;
    }
    unsigned short (*AsH)[256][24] = reinterpret_cast<unsigned short(*)[256][24]>(sbuf);

    // preload B(0), word(0)
    cp_async16(sbuf + bDstOff[0], bSrc[0]);
    cp_async16(sbuf + bDstOff[1], bSrc[1]);
    CP_COMMIT();
    unsigned rW = bitsIn[(size_t)(b * Tt + tid) * WPR + 0];

    const unsigned aRowBase = w * 32 + (lane & 15);
    const unsigned aKofs = (lane >> 4) * 16;
    const unsigned bRow = (lane & 7) + ((lane >> 4) & 1) * 8;
    const unsigned bKofs = ((lane >> 3) & 1) * 16;

    for (int c = 0; c < Hdim / 32; c++) {
        const int buf = c & 1;
        // expand word -> A smem (warp-local), both ksubs
        #pragma unroll
        for (int ksub = 0; ksub < 2; ksub++) {
            unsigned e[8];
            const unsigned sh = ksub * 16;
            #pragma unroll
            for (int i = 0; i < 8; i++) {
                unsigned q0 = (rW >> (sh + 2 * i)) & 1u;
                unsigned q1 = (rW >> (sh + 2 * i + 1)) & 1u;
                e[i] = ((q1 * 0x3F80u) << 16) | (q0 * 0x3F80u);
            }
            uint4* d = reinterpret_cast<uint4*>(&AsH[ksub][tid][0]);
            d[0] = make_uint4(e[0], e[1], e[2], e[3]);
            d[1] = make_uint4(e[4], e[5], e[6], e[7]);
        }
        if (c + 1 < Hdim / 32)
            rW = bitsIn[(size_t)(b * Tt + tid) * WPR + c + 1];
        CP_WAIT0();
        __syncthreads();
        if (c + 1 < Hdim / 32) {
            const unsigned bufOfs = (buf ^ 1) * 6144;
            cp_async16(sbuf + bDstOff[0] + bufOfs, bSrc[0] + (c + 1) * 32);
            cp_async16(sbuf + bDstOff[1] + bufOfs, bSrc[1] + (c + 1) * 32);
            CP_COMMIT();
        }
        __syncwarp();

        #pragma unroll
        for (int ksub = 0; ksub < 2; ksub++) {
            unsigned ah[2][4];
            #pragma unroll
            for (int st = 0; st < 2; st++)
                ldm4(ah[st][0], ah[st][1], ah[st][2], ah[st][3],
                     smem_u32(&AsH[ksub][aRowBase + st * 16][0]) + aKofs);
            const unsigned bBase = 24576 + buf * 6144 + ksub * 3072;
            #pragma unroll
            for (int p = 0; p < 4; p++) {
                unsigned bh[4], bl[4];
                unsigned rowOfs = (p * 16 + bRow) * 48 + bKofs;
                ldm4(bh[0], bh[1], bh[2], bh[3], smem_u32(sbuf) + bBase + rowOfs);
                ldm4(bl[0], bl[1], bl[2], bl[3], smem_u32(sbuf) + bBase + 12288 + rowOfs);
                #pragma unroll
                for (int st = 0; st < 2; st++) {
                    mma16816(acc[st][2 * p], ah[st][0], ah[st][1], ah[st][2], ah[st][3], bh[0], bh[1]);
                    mma16816(acc[st][2 * p], ah[st][0], ah[st][1], ah[st][2], ah[st][3], bl[0], bl[1]);
                    mma16816(acc[st][2 * p + 1], ah[st][0], ah[st][1], ah[st][2], ah[st][3], bh[2], bh[3]);
                    mma16816(acc[st][2 * p + 1], ah[st][0], ah[st][1], ah[st][2], ah[st][3], bl[2], bl[3]);
                }
            }
        }
    }
}

// ---------------------------------------------------------------------------
// fused2: x2 = s1 @ W2^T + b2, scan -> s2 bits
// ---------------------------------------------------------------------------
__global__ __launch_bounds__(256, 2) void fused_x2_mma(const float* __restrict__ b2) {
    __shared__ __align__(16) char sbuf[49152];
    float (*xs)[68] = reinterpret_cast<float(*)[68]>(sbuf);
    const int lane = threadIdx.x & 31;
    const int n0 = blockIdx.x * 64;
    const int b  = blockIdx.y;

    float acc[2][8][4];
    #pragma unroll
    for (int st = 0; st < 2; st++)
        #pragma unroll
        for (int ns = 0; ns < 8; ns++)
            #pragma unroll
            for (int i = 0; i < 4; i++) acc[st][ns][i] = 0.f;

    spike_gemm_body(sbuf, g_s1bits, g_W2H, g_W2L, b, n0, acc);

    {
        const int cp = 2 * (lane & 3);
        #pragma unroll
        for (int ns = 0; ns < 8; ns++) {
            float b0 = b2[n0 + ns * 8 + cp];
            float b1 = b2[n0 + ns * 8 + cp + 1];
            #pragma unroll
            for (int st = 0; st < 2; st++) {
                acc[st][ns][0] += b0; acc[st][ns][1] += b1;
                acc[st][ns][2] += b0; acc[st][ns][3] += b1;
            }
        }
    }
    scan_frags_and_pack(acc, xs, b, n0, g_s2bits);
}

// ---------------------------------------------------------------------------
// fusedM: relu(s2 @ Mw1^T + Mb1) . v -> per-n-tile logit partials
// ---------------------------------------------------------------------------
__global__ __launch_bounds__(256, 2) void fused_mil_mma(const float* __restrict__ Mb1) {
    __shared__ __align__(16) char sbuf[49152];
    const int tid = threadIdx.x;
    const int w = tid >> 5, lane = tid & 31;
    const int n0 = blockIdx.x * 64;
    const int b  = blockIdx.y;

    float acc[2][8][4];
    #pragma unroll
    for (int st = 0; st < 2; st++)
        #pragma unroll
        for (int ns = 0; ns < 8; ns++)
            #pragma unroll
            for (int i = 0; i < 4; i++) acc[st][ns][i] = 0.f;

    spike_gemm_body(sbuf, g_s2bits, g_M1H, g_M1L, b, n0, acc);

    {
        const int cp = 2 * (lane & 3);
        #pragma unroll
        for (int st = 0; st < 2; st++) {
            float p0 = 0.f, p1 = 0.f;
            #pragma unroll
            for (int ns = 0; ns < 8; ns++) {
                int col = n0 + ns * 8 + cp;
                float bb0 = Mb1[col], bb1 = Mb1[col + 1];
                float vv0 = g_v[col], vv1 = g_v[col + 1];
                float z;
                z = acc[st][ns][0] + bb0; z = z > 0.f ? z : 0.f; p0 = fmaf(z, vv0, p0);
                z = acc[st][ns][1] + bb1; z = z > 0.f ? z : 0.f; p0 = fmaf(z, vv1, p0);
                z = acc[st][ns][2] + bb0; z = z > 0.f ? z : 0.f; p1 = fmaf(z, vv0, p1);
                z = acc[st][ns][3] + bb1; z = z > 0.f ? z : 0.f; p1 = fmaf(z, vv1, p1);
            }
            p0 += __shfl_down_sync(0xffffffffu, p0, 2, 4);
            p0 += __shfl_down_sync(0xffffffffu, p0, 1, 4);
            p1 += __shfl_down_sync(0xffffffffu, p1, 2, 4);
            p1 += __shfl_down_sync(0xffffffffu, p1, 1, 4);
            if ((lane & 3) == 0) {
                int row = w * 32 + st * 16 + (lane >> 2);
                g_logitParts[(size_t)blockIdx.x * BT + b * Tt + row] = p0;
                g_logitParts[(size_t)blockIdx.x * BT + b * Tt + row + 8] = p1;
            }
        }
    }
}

// ---------------------------------------------------------------------------
// Per batch: sigmoid + top-17 mean.
// ---------------------------------------------------------------------------
__global__ void topk_kernel(float* __restrict__ out) {
    __shared__ float vals[Tt];
    __shared__ float rv[Tt];
    __shared__ int   ri[Tt];
    int b = blockIdx.x, t = threadIdx.x;
    float pre = g_cbias;
    #pragma unroll
    for (int z = 0; z < 8; z++) pre += g_logitParts[(size_t)z * BT + b * Tt + t];
    vals[t] = 1.0f / (1.0f + expf(-pre));
    __syncthreads();
    float sum = 0.f;
    for (int it = 0; it < TOPK; it++) {
        rv[t] = vals[t]; ri[t] = t;
        __syncthreads();
        for (int st = Tt / 2; st > 0; st >>= 1) {
            if (t < st && rv[t + st] > rv[t]) { rv[t] = rv[t + st]; ri[t] = ri[t + st]; }
            __syncthreads();
        }
        if (t == 0) { sum += rv[0]; vals[ri[0]] = -FLT_MAX; }
        __syncthreads();
    }
    if (t == 0) out[b] = sum / (float)TOPK;
}

// ---------------------------------------------------------------------------
namespace {
struct EnvSetup {
    EnvSetup() { setenv("CUDA_MODULE_LOADING", "EAGER", 1); }
};
EnvSetup g_env_setup;
}

// ---------------------------------------------------------------------------
extern "C" void kernel_launch(void* const* d_in, const int* in_sizes, int n_in,
                              void* d_out, int out_size) {
    (void)in_sizes; (void)n_in; (void)out_size;
    const float* f_f = (const float*)d_in[0];
    const float* Wf  = (const float*)d_in[2];
    const float* bf  = (const float*)d_in[3];
    const float* W1  = (const float*)d_in[4];
    const float* b1  = (const float*)d_in[5];
    const float* W2  = (const float*)d_in[6];
    const float* b2  = (const float*)d_in[7];
    const float* Mw1 = (const float*)d_in[8];
    const float* Mb1 = (const float*)d_in[9];
    const float* Mw2 = (const float*)d_in[10];
    const float* Mb2 = (const float*)d_in[11];
    const float* Mw3 = (const float*)d_in[12];
    const float* Mb3 = (const float*)d_in[13];
    float* out = (float*)d_out;

    // order chosen so ncu's fixed skip (lands on launch index 3) captures fused1
    prep_split_kernel<<<(FF_N / 4 + 2 * (WW_N / 4)) / 256, 256>>>(f_f, W2, Mw1);   // 0
    bc_kernel<<<Hdim, 128>>>(W1, bf, b1);                                           // 1
    wc_kernel<<<dim3(Fdim / 64, Hdim / 64), 1024>>>(W1, Wf);                        // 2
    fused_x1_mma<<<dim3(Hdim / 64, Bb), 256>>>();                                   // 3 <- profiled
    vc_kernel<<<2, 256>>>(Mw2, Mb2, Mw3, Mb3);                                      // 4
    fused_x2_mma<<<dim3(Hdim / 64, Bb), 256>>>(b2);                                 // 5
    fused_mil_mma<<<dim3(Hdim / 64, Bb), 256>>>(Mb1);                               // 6
    topk_kernel<<<Bb, Tt>>>(out);                                                   // 7
}

// round 13
// speedup vs baseline: 1.2453x; 1.2453x over previous
#include <cuda_runtime.h>
#include <cuda_bf16.h>
#include <math.h>
#include <float.h>
#include <stdlib.h>

// ---------------------------------------------------------------------------
// snn_test: B=64, T=256, F=1024, H=512 — bf16 MMA v5
//   prep:   split f_f -> bf16 hi/lo in CHUNK-MAJOR layout [b][kchunk][t][16]
//           (A loads in fused1 become fully coalesced); W2, Mw1 hi/lo split
//   wc:     Wc = W1 @ Wf (fp32, 1024 thr, 4-way in-block split-K) -> hi/lo
//   fused1: x1 = f_f @ Wc^T + bc (3-pass split bf16; A via coalesced cp.async,
//           warp-private single-buffer; B cp.async double-buffer) -> scan -> s1
//   fused2: x2 = s1 @ W2^T + b2 (2-pass) -> scan -> s2 bits
//   fusedM: relu(s2 @ Mw1^T + Mb1) . v (2-pass) -> logit partials
//   topk:   sigmoid + top-17 mean
// Launch order keeps fused1 at index 3 for ncu capture.
// ---------------------------------------------------------------------------

constexpr int Bb   = 64;
constexpr int Tt   = 256;
constexpr int Fdim = 1024;
constexpr int Hdim = 512;
constexpr int BT   = Bb * Tt;
constexpr int TOPK = Tt / 16 + 1;      // 17
constexpr int WPR  = Hdim / 32;        // 16
constexpr int FF_N = Bb * Tt * Fdim;   // 16,777,216
constexpr int WW_N = Hdim * Hdim;      // 262,144

// ---- device-global scratch (~41 MB) ----
__device__ __nv_bfloat16 g_ffH[FF_N];   // chunk-major [b][kchunk(64)][t(256)][16]
__device__ __nv_bfloat16 g_ffL[FF_N];
__device__ __nv_bfloat16 g_WcH[Hdim * Fdim];
__device__ __nv_bfloat16 g_WcL[Hdim * Fdim];
__device__ __nv_bfloat16 g_W2H[WW_N];
__device__ __nv_bfloat16 g_W2L[WW_N];
__device__ __nv_bfloat16 g_M1H[WW_N];
__device__ __nv_bfloat16 g_M1L[WW_N];
__device__ float    g_bc[Hdim];
__device__ float    g_v[Hdim];
__device__ float    g_cbias;
__device__ unsigned g_s1bits[BT * WPR];
__device__ unsigned g_s2bits[BT * WPR];
__device__ float    g_logitParts[8 * BT];

// ---------------------------------------------------------------------------
// PTX helpers
// ---------------------------------------------------------------------------
__device__ __forceinline__ unsigned smem_u32(const void* p) {
    return (unsigned)__cvta_generic_to_shared(p);
}
__device__ __forceinline__ void ldm4(unsigned& r0, unsigned& r1, unsigned& r2, unsigned& r3,
                                     unsigned addr) {
    asm volatile("ldmatrix.sync.aligned.m8n8.x4.shared.b16 {%0,%1,%2,%3},[%4];"
                 : "=r"(r0), "=r"(r1), "=r"(r2), "=r"(r3) : "r"(addr));
}
__device__ __forceinline__ void mma16816(float* c, unsigned a0, unsigned a1, unsigned a2,
                                         unsigned a3, unsigned b0, unsigned b1) {
    asm volatile(
        "mma.sync.aligned.m16n8k16.row.col.f32.bf16.bf16.f32 "
        "{%0,%1,%2,%3},{%4,%5,%6,%7},{%8,%9},{%0,%1,%2,%3};"
        : "+f"(c[0]), "+f"(c[1]), "+f"(c[2]), "+f"(c[3])
        : "r"(a0), "r"(a1), "r"(a2), "r"(a3), "r"(b0), "r"(b1));
}
__device__ __forceinline__ void cp_async16(void* sdst, const void* gsrc) {
    asm volatile("cp.async.ca.shared.global [%0],[%1],16;"
                 :: "r"(smem_u32(sdst)), "l"(gsrc));
}
#define CP_COMMIT() asm volatile("cp.async.commit_group;")
#define CP_WAIT0()  asm volatile("cp.async.wait_group 0;")

// ---------------------------------------------------------------------------
// prep: hi/lo split. f_f -> chunk-major; W2/Mw1 -> row-major (unchanged).
// ---------------------------------------------------------------------------
__device__ __forceinline__ void split4(float4 v, uint2& H, uint2& L) {
    __nv_bfloat16 h0 = __float2bfloat16_rn(v.x), h1 = __float2bfloat16_rn(v.y);
    __nv_bfloat16 h2 = __float2bfloat16_rn(v.z), h3 = __float2bfloat16_rn(v.w);
    __nv_bfloat16 l0 = __float2bfloat16_rn(v.x - __bfloat162float(h0));
    __nv_bfloat16 l1 = __float2bfloat16_rn(v.y - __bfloat162float(h1));
    __nv_bfloat16 l2 = __float2bfloat16_rn(v.z - __bfloat162float(h2));
    __nv_bfloat16 l3 = __float2bfloat16_rn(v.w - __bfloat162float(h3));
    H.x = ((unsigned)__bfloat16_as_ushort(h1) << 16) | __bfloat16_as_ushort(h0);
    H.y = ((unsigned)__bfloat16_as_ushort(h3) << 16) | __bfloat16_as_ushort(h2);
    L.x = ((unsigned)__bfloat16_as_ushort(l1) << 16) | __bfloat16_as_ushort(l0);
    L.y = ((unsigned)__bfloat16_as_ushort(l3) << 16) | __bfloat16_as_ushort(l2);
}

__global__ void prep_split_kernel(const float* __restrict__ f_f,
                                  const float* __restrict__ W2,
                                  const float* __restrict__ Mw1) {
    const int FF4 = FF_N / 4, WW4 = WW_N / 4;
    int i = blockIdx.x * 256 + threadIdx.x;
    uint2 H, L;
    if (i < FF4) {
        split4(reinterpret_cast<const float4*>(f_f)[i], H, L);
        int idx = i * 4;
        int b   = idx >> 18;        // / (Tt*Fdim)
        int rem = idx & 262143;
        int t   = rem >> 10;        // / Fdim
        int f   = rem & 1023;
        size_t dst = ((size_t)b << 18) + ((size_t)(f >> 4) << 12) + (t << 4) + (f & 15);
        *reinterpret_cast<uint2*>(g_ffH + dst) = H;
        *reinterpret_cast<uint2*>(g_ffL + dst) = L;
    } else if (i < FF4 + WW4) {
        int j = i - FF4;
        split4(reinterpret_cast<const float4*>(W2)[j], H, L);
        reinterpret_cast<uint2*>(g_W2H)[j] = H;
        reinterpret_cast<uint2*>(g_W2L)[j] = L;
    } else {
        int j = i - FF4 - WW4;
        split4(reinterpret_cast<const float4*>(Mw1)[j], H, L);
        reinterpret_cast<uint2*>(g_M1H)[j] = H;
        reinterpret_cast<uint2*>(g_M1L)[j] = L;
    }
}

// ---------------------------------------------------------------------------
// bc[n] = W1[n,:]·bf + b1[n]
// ---------------------------------------------------------------------------
__global__ void bc_kernel(const float* __restrict__ W1, const float* __restrict__ bf,
                          const float* __restrict__ b1) {
    __shared__ float red[128];
    int n = blockIdx.x;
    float s = 0.f;
    for (int j = threadIdx.x; j < Hdim; j += 128)
        s = fmaf(W1[n * Hdim + j], bf[j], s);
    red[threadIdx.x] = s;
    __syncthreads();
    for (int st = 64; st > 0; st >>= 1) {
        if (threadIdx.x < st) red[threadIdx.x] += red[threadIdx.x + st];
        __syncthreads();
    }
    if (threadIdx.x == 0) g_bc[n] = red[0] + b1[n];
}

// ---------------------------------------------------------------------------
// v[j] = Mw3 · Mw2[:,j];  cbias = Mw3·Mb2 + Mb3
// ---------------------------------------------------------------------------
__global__ void vc_kernel(const float* __restrict__ Mw2, const float* __restrict__ Mb2,
                          const float* __restrict__ Mw3, const float* __restrict__ Mb3) {
    int j = blockIdx.x * blockDim.x + threadIdx.x;
    if (j < Hdim) {
        float s = 0.f;
        #pragma unroll
        for (int k = 0; k < 32; k++) s = fmaf(Mw3[k], Mw2[k * Hdim + j], s);
        g_v[j] = s;
    }
    if (j == 0) {
        float c = Mb3[0];
        #pragma unroll
        for (int k = 0; k < 32; k++) c = fmaf(Mw3[k], Mb2[k], c);
        g_cbias = c;
    }
}

// ---------------------------------------------------------------------------
// Wc = W1 @ Wf (fp32, 64x64 tile, 1024 thr, 4-way in-block split-K).
// ---------------------------------------------------------------------------
__global__ __launch_bounds__(1024) void wc_kernel(const float* __restrict__ W1,
                                                  const float* __restrict__ Wf) {
    __shared__ float sm[8704];
    const int tid = threadIdx.x;
    const int g = tid >> 8;
    const int t = tid & 255;
    const int tym = t >> 4, txn = t & 15;
    const int m0 = blockIdx.y * 64, n0 = blockIdx.x * 64;
    float* Asg = sm + g * 2176;
    float* Bsg = Asg + 1088;
    float acc[4][4];
    #pragma unroll
    for (int i = 0; i < 4; i++)
        #pragma unroll
        for (int j = 0; j < 4; j++) acc[i][j] = 0.f;

    const int kbase = g * 128;
    for (int kt = 0; kt < 128; kt += 16) {
        const int k = kbase + kt;
        {
            int r = t >> 2, c = (t & 3) * 4;
            const float4 v = *reinterpret_cast<const float4*>(W1 + (size_t)(m0 + r) * Hdim + k + c);
            Asg[(c + 0) * 68 + r] = v.x; Asg[(c + 1) * 68 + r] = v.y;
            Asg[(c + 2) * 68 + r] = v.z; Asg[(c + 3) * 68 + r] = v.w;
        }
        {
            int kr = t >> 4, cc = (t & 15) * 4;
            const float4 v = *reinterpret_cast<const float4*>(Wf + (size_t)(k + kr) * Fdim + n0 + cc);
            *reinterpret_cast<float4*>(&Bsg[kr * 68 + cc]) = v;
        }
        __syncthreads();
        #pragma unroll
        for (int kk = 0; kk < 16; kk++) {
            float a[4], b[4];
            #pragma unroll
            for (int i = 0; i < 4; i++) a[i] = Asg[kk * 68 + tym * 4 + i];
            #pragma unroll
            for (int j = 0; j < 4; j++) b[j] = Bsg[kk * 68 + txn * 4 + j];
            #pragma unroll
            for (int i = 0; i < 4; i++)
                #pragma unroll
                for (int j = 0; j < 4; j++)
                    acc[i][j] = fmaf(a[i], b[j], acc[i][j]);
        }
        __syncthreads();
    }
    float* part0 = sm;
    float* part1 = sm + 4352;
    __syncthreads();
    if (g == 1 || g == 3) {
        float* p = (g == 1) ? part0 : part1;
        #pragma unroll
        for (int i = 0; i < 4; i++)
            #pragma unroll
            for (int j = 0; j < 4; j++)
                p[(tym * 4 + i) * 68 + txn * 4 + j] = acc[i][j];
    }
    __syncthreads();
    if (g == 0)
        #pragma unroll
        for (int i = 0; i < 4; i++)
            #pragma unroll
            for (int j = 0; j < 4; j++)
                acc[i][j] += part0[(tym * 4 + i) * 68 + txn * 4 + j];
    if (g == 2)
        #pragma unroll
        for (int i = 0; i < 4; i++)
            #pragma unroll
            for (int j = 0; j < 4; j++)
                acc[i][j] += part1[(tym * 4 + i) * 68 + txn * 4 + j];
    __syncthreads();
    if (g == 2) {
        #pragma unroll
        for (int i = 0; i < 4; i++)
            #pragma unroll
            for (int j = 0; j < 4; j++)
                part0[(tym * 4 + i) * 68 + txn * 4 + j] = acc[i][j];
    }
    __syncthreads();
    if (g == 0) {
        #pragma unroll
        for (int i = 0; i < 4; i++)
            #pragma unroll
            for (int j = 0; j < 4; j++) {
                float v = acc[i][j] + part0[(tym * 4 + i) * 68 + txn * 4 + j];
                size_t off = (size_t)(m0 + tym * 4 + i) * Fdim + n0 + txn * 4 + j;
                __nv_bfloat16 h = __float2bfloat16_rn(v);
                g_WcH[off] = h;
                g_WcL[off] = __float2bfloat16_rn(v - __bfloat162float(h));
            }
    }
}

// ---------------------------------------------------------------------------
// Fragment scan + bit-pack
// ---------------------------------------------------------------------------
__device__ __forceinline__ void scan_frags_and_pack(
    float (&acc)[2][8][4], float (*xs)[68],
    int b, int n0, unsigned* __restrict__ bits_out)
{
    const int tid = threadIdx.x;
    const int w = tid >> 5, lane = tid & 31;
    const int q = lane >> 2, cp = 2 * (lane & 3);
    float m = 0.f;
    __syncthreads();
    #pragma unroll
    for (int c = 0; c < 4; c++) {
        if ((w >> 1) == c) {
            const int rb = (w & 1) * 32;
            #pragma unroll
            for (int st = 0; st < 2; st++) {
                #pragma unroll
                for (int ns = 0; ns < 8; ns++) {
                    int r = rb + st * 16 + q;
                    int col = ns * 8 + cp;
                    xs[r][col]         = acc[st][ns][0];
                    xs[r][col + 1]     = acc[st][ns][1];
                    xs[r + 8][col]     = acc[st][ns][2];
                    xs[r + 8][col + 1] = acc[st][ns][3];
                }
            }
        }
        __syncthreads();
        if (w < 2) {
            for (int tt = 0; tt < 64; tt++) {
                float x = xs[tt][w * 32 + lane];
                float r = (m > 1.0f) ? 1.0f : 0.0f;
                m = 0.9f * m + x - r;
                unsigned bits = __ballot_sync(0xffffffffu, m > 1.0f);
                if (lane == 0)
                    bits_out[(size_t)(b * Tt + c * 64 + tt) * WPR + (n0 >> 5) + w] = bits;
            }
        }
        __syncthreads();
    }
}

// ---------------------------------------------------------------------------
// fused1: x1 = f_f[b] @ Wc^T + bc (3-pass), scan -> s1 bits.
// A: coalesced cp.async from chunk-major gmem into warp-private single buffer.
// B: cp.async double-buffered. One block sync per chunk.
// smem: AsH [256][24] @0 (12KB), AsL @12288, BsH[2][64][24] @24576 (6KB),
//       BsL[2][64][24] @30720 (6KB). Total 36KB. xs aliases A.
// ---------------------------------------------------------------------------
__global__ __launch_bounds__(256, 2) void fused_x1_mma() {
    __shared__ __align__(16) char sbuf[36864];
    float (*xs)[68] = reinterpret_cast<float(*)[68]>(sbuf);

    const int tid = threadIdx.x;
    const int w = tid >> 5, lane = tid & 31;
    const int n0 = blockIdx.x * 64;
    const int b  = blockIdx.y;

    float acc[2][8][4];
    #pragma unroll
    for (int st = 0; st < 2; st++)
        #pragma unroll
        for (int ns = 0; ns < 8; ns++)
            #pragma unroll
            for (int i = 0; i < 4; i++) acc[st][ns][i] = 0.f;

    // B cp.async mapping (tid<128 -> hi, else lo); buf stride 3072B
    const int brow = (tid & 127) >> 1, bseg = tid & 1;
    const __nv_bfloat16* gsrcB = ((tid < 128) ? g_WcH : g_WcL)
                                 + (size_t)(n0 + brow) * Fdim + bseg * 8;
    char* bDst = sbuf + 24576 + ((tid < 128) ? 0 : 6144) + brow * 48 + bseg * 16;

    // A cp.async mapping: thread writes its own row (tid), both 16B segs, hi+lo
    const __nv_bfloat16* gsrcAH = g_ffH + ((size_t)b << 18) + tid * 16;
    const __nv_bfloat16* gsrcAL = g_ffL + ((size_t)b << 18) + tid * 16;
    char* aDstH = sbuf + tid * 48;
    char* aDstL = sbuf + 12288 + tid * 48;

    // preload chunk 0 (A + B in one group)
    cp_async16(aDstH,      gsrcAH);
    cp_async16(aDstH + 16, gsrcAH + 8);
    cp_async16(aDstL,      gsrcAL);
    cp_async16(aDstL + 16, gsrcAL + 8);
    cp_async16(bDst, gsrcB);
    CP_COMMIT();

    const unsigned sb = smem_u32(sbuf);
    const unsigned aRow = (w * 32 + (lane & 15)) * 48 + (lane >> 4) * 16;
    const unsigned bRow = (lane & 7) + ((lane >> 4) & 1) * 8;
    const unsigned bKofs = ((lane >> 3) & 1) * 16;

    for (int c = 0; c < Fdim / 16; c++) {
        const int buf = c & 1;
        CP_WAIT0();           // A(c) + B(c) arrived (this thread's groups)
        __syncthreads();      // cross-thread visibility; prior-buf reads done
        if (c + 1 < Fdim / 16) {
            cp_async16(bDst + (buf ^ 1) * 3072, gsrcB + (c + 1) * 16);
            CP_COMMIT();
        }
        // A fragments for chunk c (single buffer, warp-private rows)
        unsigned ah[2][4], al[2][4];
        #pragma unroll
        for (int st = 0; st < 2; st++) {
            ldm4(ah[st][0], ah[st][1], ah[st][2], ah[st][3], sb + aRow + st * 768);
            ldm4(al[st][0], al[st][1], al[st][2], al[st][3], sb + 12288 + aRow + st * 768);
        }
        __syncwarp();         // all lanes finished reading A(c) rows
        if (c + 1 < Fdim / 16) {
            const int kofs = (c + 1) * 4096;   // elements per chunk
            cp_async16(aDstH,      gsrcAH + kofs);
            cp_async16(aDstH + 16, gsrcAH + kofs + 8);
            cp_async16(aDstL,      gsrcAL + kofs);
            cp_async16(aDstL + 16, gsrcAL + kofs + 8);
            CP_COMMIT();
        }
        // B fragments + MMA (3-pass)
        const unsigned bB = sb + 24576 + buf * 3072;
        #pragma unroll
        for (int p = 0; p < 4; p++) {
            unsigned bh[4], bl[4];
            const unsigned rowOfs = (p * 16 + bRow) * 48 + bKofs;
            ldm4(bh[0], bh[1], bh[2], bh[3], bB + rowOfs);
            ldm4(bl[0], bl[1], bl[2], bl[3], bB + 6144 + rowOfs);
            #pragma unroll
            for (int st = 0; st < 2; st++) {
                mma16816(acc[st][2 * p], ah[st][0], ah[st][1], ah[st][2], ah[st][3], bh[0], bh[1]);
                mma16816(acc[st][2 * p], ah[st][0], ah[st][1], ah[st][2], ah[st][3], bl[0], bl[1]);
                mma16816(acc[st][2 * p], al[st][0], al[st][1], al[st][2], al[st][3], bh[0], bh[1]);
                mma16816(acc[st][2 * p + 1], ah[st][0], ah[st][1], ah[st][2], ah[st][3], bh[2], bh[3]);
                mma16816(acc[st][2 * p + 1], ah[st][0], ah[st][1], ah[st][2], ah[st][3], bl[2], bl[3]);
                mma16816(acc[st][2 * p + 1], al[st][0], al[st][1], al[st][2], al[st][3], bh[2], bh[3]);
            }
        }
    }
    {
        const int cp = 2 * (lane & 3);
        #pragma unroll
        for (int ns = 0; ns < 8; ns++) {
            float b0 = g_bc[n0 + ns * 8 + cp];
            float b1 = g_bc[n0 + ns * 8 + cp + 1];
            #pragma unroll
            for (int st = 0; st < 2; st++) {
                acc[st][ns][0] += b0; acc[st][ns][1] += b1;
                acc[st][ns][2] += b0; acc[st][ns][3] += b1;
            }
        }
    }
    scan_frags_and_pack(acc, xs, b, n0, g_s1bits);
}

// ---------------------------------------------------------------------------
// Shared body for fused2 / fusedM: A from spike bits, 32-k chunks, 2-pass B.
// ---------------------------------------------------------------------------
__device__ __forceinline__ void spike_gemm_body(
    char* sbuf, const unsigned* __restrict__ bitsIn,
    const __nv_bfloat16* __restrict__ WH, const __nv_bfloat16* __restrict__ WL,
    int b, int n0, float (&acc)[2][8][4])
{
    const int tid = threadIdx.x;
    const int w = tid >> 5, lane = tid & 31;

    unsigned bDstOff[2];
    const __nv_bfloat16* bSrc[2];
    #pragma unroll
    for (int j = 0; j < 2; j++) {
        int u = tid * 2 + j;
        int hl = u >> 8, r = u & 255;
        int ksub = r >> 7, rr = r & 127;
        int row = rr >> 1, seg = rr & 1;
        bDstOff[j] = 24576 + hl * 12288 + ksub * 3072 + row * 48 + seg * 16;
        bSrc[j] = (hl ? WL : WH) + (size_t)(n0 + row) * Hdim + ksub * 16 + seg * 8;
    }
    unsigned short (*AsH)[256][24] = reinterpret_cast<unsigned short(*)[256][24]>(sbuf);

    cp_async16(sbuf + bDstOff[0], bSrc[0]);
    cp_async16(sbuf + bDstOff[1], bSrc[1]);
    CP_COMMIT();
    unsigned rW = bitsIn[(size_t)(b * Tt + tid) * WPR + 0];

    const unsigned aRowBase = w * 32 + (lane & 15);
    const unsigned aKofs = (lane >> 4) * 16;
    const unsigned bRow = (lane & 7) + ((lane >> 4) & 1) * 8;
    const unsigned bKofs = ((lane >> 3) & 1) * 16;

    for (int c = 0; c < Hdim / 32; c++) {
        const int buf = c & 1;
        #pragma unroll
        for (int ksub = 0; ksub < 2; ksub++) {
            unsigned e[8];
            const unsigned sh = ksub * 16;
            #pragma unroll
            for (int i = 0; i < 8; i++) {
                unsigned q0 = (rW >> (sh + 2 * i)) & 1u;
                unsigned q1 = (rW >> (sh + 2 * i + 1)) & 1u;
                e[i] = ((q1 * 0x3F80u) << 16) | (q0 * 0x3F80u);
            }
            uint4* d = reinterpret_cast<uint4*>(&AsH[ksub][tid][0]);
            d[0] = make_uint4(e[0], e[1], e[2], e[3]);
            d[1] = make_uint4(e[4], e[5], e[6], e[7]);
        }
        if (c + 1 < Hdim / 32)
            rW = bitsIn[(size_t)(b * Tt + tid) * WPR + c + 1];
        CP_WAIT0();
        __syncthreads();
        if (c + 1 < Hdim / 32) {
            const unsigned bufOfs = (buf ^ 1) * 6144;
            cp_async16(sbuf + bDstOff[0] + bufOfs, bSrc[0] + (c + 1) * 32);
            cp_async16(sbuf + bDstOff[1] + bufOfs, bSrc[1] + (c + 1) * 32);
            CP_COMMIT();
        }
        __syncwarp();

        #pragma unroll
        for (int ksub = 0; ksub < 2; ksub++) {
            unsigned ah[2][4];
            #pragma unroll
            for (int st = 0; st < 2; st++)
                ldm4(ah[st][0], ah[st][1], ah[st][2], ah[st][3],
                     smem_u32(&AsH[ksub][aRowBase + st * 16][0]) + aKofs);
            const unsigned bBase = 24576 + buf * 6144 + ksub * 3072;
            #pragma unroll
            for (int p = 0; p < 4; p++) {
                unsigned bh[4], bl[4];
                unsigned rowOfs = (p * 16 + bRow) * 48 + bKofs;
                ldm4(bh[0], bh[1], bh[2], bh[3], smem_u32(sbuf) + bBase + rowOfs);
                ldm4(bl[0], bl[1], bl[2], bl[3], smem_u32(sbuf) + bBase + 12288 + rowOfs);
                #pragma unroll
                for (int st = 0; st < 2; st++) {
                    mma16816(acc[st][2 * p], ah[st][0], ah[st][1], ah[st][2], ah[st][3], bh[0], bh[1]);
                    mma16816(acc[st][2 * p], ah[st][0], ah[st][1], ah[st][2], ah[st][3], bl[0], bl[1]);
                    mma16816(acc[st][2 * p + 1], ah[st][0], ah[st][1], ah[st][2], ah[st][3], bh[2], bh[3]);
                    mma16816(acc[st][2 * p + 1], ah[st][0], ah[st][1], ah[st][2], ah[st][3], bl[2], bl[3]);
                }
            }
        }
    }
}

// ---------------------------------------------------------------------------
// fused2: x2 = s1 @ W2^T + b2, scan -> s2 bits
// ---------------------------------------------------------------------------
__global__ __launch_bounds__(256, 2) void fused_x2_mma(const float* __restrict__ b2) {
    __shared__ __align__(16) char sbuf[49152];
    float (*xs)[68] = reinterpret_cast<float(*)[68]>(sbuf);
    const int lane = threadIdx.x & 31;
    const int n0 = blockIdx.x * 64;
    const int b  = blockIdx.y;

    float acc[2][8][4];
    #pragma unroll
    for (int st = 0; st < 2; st++)
        #pragma unroll
        for (int ns = 0; ns < 8; ns++)
            #pragma unroll
            for (int i = 0; i < 4; i++) acc[st][ns][i] = 0.f;

    spike_gemm_body(sbuf, g_s1bits, g_W2H, g_W2L, b, n0, acc);

    {
        const int cp = 2 * (lane & 3);
        #pragma unroll
        for (int ns = 0; ns < 8; ns++) {
            float b0 = b2[n0 + ns * 8 + cp];
            float b1 = b2[n0 + ns * 8 + cp + 1];
            #pragma unroll
            for (int st = 0; st < 2; st++) {
                acc[st][ns][0] += b0; acc[st][ns][1] += b1;
                acc[st][ns][2] += b0; acc[st][ns][3] += b1;
            }
        }
    }
    scan_frags_and_pack(acc, xs, b, n0, g_s2bits);
}

// ---------------------------------------------------------------------------
// fusedM: relu(s2 @ Mw1^T + Mb1) . v -> per-n-tile logit partials
// ---------------------------------------------------------------------------
__global__ __launch_bounds__(256, 2) void fused_mil_mma(const float* __restrict__ Mb1) {
    __shared__ __align__(16) char sbuf[49152];
    const int tid = threadIdx.x;
    const int w = tid >> 5, lane = tid & 31;
    const int n0 = blockIdx.x * 64;
    const int b  = blockIdx.y;

    float acc[2][8][4];
    #pragma unroll
    for (int st = 0; st < 2; st++)
        #pragma unroll
        for (int ns = 0; ns < 8; ns++)
            #pragma unroll
            for (int i = 0; i < 4; i++) acc[st][ns][i] = 0.f;

    spike_gemm_body(sbuf, g_s2bits, g_M1H, g_M1L, b, n0, acc);

    {
        const int cp = 2 * (lane & 3);
        #pragma unroll
        for (int st = 0; st < 2; st++) {
            float p0 = 0.f, p1 = 0.f;
            #pragma unroll
            for (int ns = 0; ns < 8; ns++) {
                int col = n0 + ns * 8 + cp;
                float bb0 = Mb1[col], bb1 = Mb1[col + 1];
                float vv0 = g_v[col], vv1 = g_v[col + 1];
                float z;
                z = acc[st][ns][0] + bb0; z = z > 0.f ? z : 0.f; p0 = fmaf(z, vv0, p0);
                z = acc[st][ns][1] + bb1; z = z > 0.f ? z : 0.f; p0 = fmaf(z, vv1, p0);
                z = acc[st][ns][2] + bb0; z = z > 0.f ? z : 0.f; p1 = fmaf(z, vv0, p1);
                z = acc[st][ns][3] + bb1; z = z > 0.f ? z : 0.f; p1 = fmaf(z, vv1, p1);
            }
            p0 += __shfl_down_sync(0xffffffffu, p0, 2, 4);
            p0 += __shfl_down_sync(0xffffffffu, p0, 1, 4);
            p1 += __shfl_down_sync(0xffffffffu, p1, 2, 4);
            p1 += __shfl_down_sync(0xffffffffu, p1, 1, 4);
            if ((lane & 3) == 0) {
                int row = w * 32 + st * 16 + (lane >> 2);
                g_logitParts[(size_t)blockIdx.x * BT + b * Tt + row] = p0;
                g_logitParts[(size_t)blockIdx.x * BT + b * Tt + row + 8] = p1;
            }
        }
    }
}

// ---------------------------------------------------------------------------
// Per batch: sigmoid + top-17 mean.
// ---------------------------------------------------------------------------
__global__ void topk_kernel(float* __restrict__ out) {
    __shared__ float vals[Tt];
    __shared__ float rv[Tt];
    __shared__ int   ri[Tt];
    int b = blockIdx.x, t = threadIdx.x;
    float pre = g_cbias;
    #pragma unroll
    for (int z = 0; z < 8; z++) pre += g_logitParts[(size_t)z * BT + b * Tt + t];
    vals[t] = 1.0f / (1.0f + expf(-pre));
    __syncthreads();
    float sum = 0.f;
    for (int it = 0; it < TOPK; it++) {
        rv[t] = vals[t]; ri[t] = t;
        __syncthreads();
        for (int st = Tt / 2; st > 0; st >>= 1) {
            if (t < st && rv[t + st] > rv[t]) { rv[t] = rv[t + st]; ri[t] = ri[t + st]; }
            __syncthreads();
        }
        if (t == 0) { sum += rv[0]; vals[ri[0]] = -FLT_MAX; }
        __syncthreads();
    }
    if (t == 0) out[b] = sum / (float)TOPK;
}

// ---------------------------------------------------------------------------
namespace {
struct EnvSetup {
    EnvSetup() { setenv("CUDA_MODULE_LOADING", "EAGER", 1); }
};
EnvSetup g_env_setup;
}

// ---------------------------------------------------------------------------
extern "C" void kernel_launch(void* const* d_in, const int* in_sizes, int n_in,
                              void* d_out, int out_size) {
    (void)in_sizes; (void)n_in; (void)out_size;
    const float* f_f = (const float*)d_in[0];
    const float* Wf  = (const float*)d_in[2];
    const float* bf  = (const float*)d_in[3];
    const float* W1  = (const float*)d_in[4];
    const float* b1  = (const float*)d_in[5];
    const float* W2  = (const float*)d_in[6];
    const float* b2  = (const float*)d_in[7];
    const float* Mw1 = (const float*)d_in[8];
    const float* Mb1 = (const float*)d_in[9];
    const float* Mw2 = (const float*)d_in[10];
    const float* Mb2 = (const float*)d_in[11];
    const float* Mw3 = (const float*)d_in[12];
    const float* Mb3 = (const float*)d_in[13];
    float* out = (float*)d_out;

    prep_split_kernel<<<(FF_N / 4 + 2 * (WW_N / 4)) / 256, 256>>>(f_f, W2, Mw1);   // 0
    bc_kernel<<<Hdim, 128>>>(W1, bf, b1);                                           // 1
    wc_kernel<<<dim3(Fdim / 64, Hdim / 64), 1024>>>(W1, Wf);                        // 2
    fused_x1_mma<<<dim3(Hdim / 64, Bb), 256>>>();                                   // 3 <- profiled
    vc_kernel<<<2, 256>>>(Mw2, Mb2, Mw3, Mb3);                                      // 4
    fused_x2_mma<<<dim3(Hdim / 64, Bb), 256>>>(b2);                                 // 5
    fused_mil_mma<<<dim3(Hdim / 64, Bb), 256>>>(Mb1);                               // 6
    topk_kernel<<<Bb, Tt>>>(out);                                                   // 7
}

// round 14
// speedup vs baseline: 1.2522x; 1.0055x over previous
#include <cuda_runtime.h>
#include <cuda_bf16.h>
#include <math.h>
#include <float.h>
#include <stdlib.h>

// ---------------------------------------------------------------------------
// snn_test: B=64, T=256, F=1024, H=512 — bf16 MMA v5
//   prep:   split f_f -> bf16 hi/lo in CHUNK-MAJOR layout [b][kchunk][t][16]
//           (A loads in fused1 become fully coalesced); W2, Mw1 hi/lo split
//   wc:     Wc = W1 @ Wf (fp32, 1024 thr, 4-way in-block split-K) -> hi/lo
//   fused1: x1 = f_f @ Wc^T + bc (3-pass split bf16; A via coalesced cp.async,
//           warp-private single-buffer; B cp.async double-buffer) -> scan -> s1
//   fused2: x2 = s1 @ W2^T + b2 (2-pass) -> scan -> s2 bits
//   fusedM: relu(s2 @ Mw1^T + Mb1) . v (2-pass) -> logit partials
//   topk:   sigmoid + top-17 mean
// Launch order keeps fused1 at index 3 for ncu capture.
// ---------------------------------------------------------------------------

constexpr int Bb   = 64;
constexpr int Tt   = 256;
constexpr int Fdim = 1024;
constexpr int Hdim = 512;
constexpr int BT   = Bb * Tt;
constexpr int TOPK = Tt / 16 + 1;      // 17
constexpr int WPR  = Hdim / 32;        // 16
constexpr int FF_N = Bb * Tt * Fdim;   // 16,777,216
constexpr int WW_N = Hdim * Hdim;      // 262,144

// ---- device-global scratch (~41 MB) ----
__device__ __nv_bfloat16 g_ffH[FF_N];   // chunk-major [b][kchunk(64)][t(256)][16]
__device__ __nv_bfloat16 g_ffL[FF_N];
__device__ __nv_bfloat16 g_WcH[Hdim * Fdim];
__device__ __nv_bfloat16 g_WcL[Hdim * Fdim];
__device__ __nv_bfloat16 g_W2H[WW_N];
__device__ __nv_bfloat16 g_W2L[WW_N];
__device__ __nv_bfloat16 g_M1H[WW_N];
__device__ __nv_bfloat16 g_M1L[WW_N];
__device__ float    g_bc[Hdim];
__device__ float    g_v[Hdim];
__device__ float    g_cbias;
__device__ unsigned g_s1bits[BT * WPR];
__device__ unsigned g_s2bits[BT * WPR];
__device__ float    g_logitParts[8 * BT];

// ---------------------------------------------------------------------------
// PTX helpers
// ---------------------------------------------------------------------------
__device__ __forceinline__ unsigned smem_u32(const void* p) {
    return (unsigned)__cvta_generic_to_shared(p);
}
__device__ __forceinline__ void ldm4(unsigned& r0, unsigned& r1, unsigned& r2, unsigned& r3,
                                     unsigned addr) {
    asm volatile("ldmatrix.sync.aligned.m8n8.x4.shared.b16 {%0,%1,%2,%3},[%4];"
                 : "=r"(r0), "=r"(r1), "=r"(r2), "=r"(r3) : "r"(addr));
}
__device__ __forceinline__ void mma16816(float* c, unsigned a0, unsigned a1, unsigned a2,
                                         unsigned a3, unsigned b0, unsigned b1) {
    asm volatile(
        "mma.sync.aligned.m16n8k16.row.col.f32.bf16.bf16.f32 "
        "{%0,%1,%2,%3},{%4,%5,%6,%7},{%8,%9},{%0,%1,%2,%3};"
        : "+f"(c[0]), "+f"(c[1]), "+f"(c[2]), "+f"(c[3])
        : "r"(a0), "r"(a1), "r"(a2), "r"(a3), "r"(b0), "r"(b1));
}
__device__ __forceinline__ void cp_async16(void* sdst, const void* gsrc) {
    asm volatile("cp.async.ca.shared.global [%0],[%1],16;"
                 :: "r"(smem_u32(sdst)), "l"(gsrc));
}
#define CP_COMMIT() asm volatile("cp.async.commit_group;")
#define CP_WAIT0()  asm volatile("cp.async.wait_group 0;")

// ---------------------------------------------------------------------------
// prep: hi/lo split. f_f -> chunk-major; W2/Mw1 -> row-major (unchanged).
// ---------------------------------------------------------------------------
__device__ __forceinline__ void split4(float4 v, uint2& H, uint2& L) {
    __nv_bfloat16 h0 = __float2bfloat16_rn(v.x), h1 = __float2bfloat16_rn(v.y);
    __nv_bfloat16 h2 = __float2bfloat16_rn(v.z), h3 = __float2bfloat16_rn(v.w);
    __nv_bfloat16 l0 = __float2bfloat16_rn(v.x - __bfloat162float(h0));
    __nv_bfloat16 l1 = __float2bfloat16_rn(v.y - __bfloat162float(h1));
    __nv_bfloat16 l2 = __float2bfloat16_rn(v.z - __bfloat162float(h2));
    __nv_bfloat16 l3 = __float2bfloat16_rn(v.w - __bfloat162float(h3));
    H.x = ((unsigned)__bfloat16_as_ushort(h1) << 16) | __bfloat16_as_ushort(h0);
    H.y = ((unsigned)__bfloat16_as_ushort(h3) << 16) | __bfloat16_as_ushort(h2);
    L.x = ((unsigned)__bfloat16_as_ushort(l1) << 16) | __bfloat16_as_ushort(l0);
    L.y = ((unsigned)__bfloat16_as_ushort(l3) << 16) | __bfloat16_as_ushort(l2);
}

__global__ void prep_split_kernel(const float* __restrict__ f_f,
                                  const float* __restrict__ W2,
                                  const float* __restrict__ Mw1) {
    const int FF4 = FF_N / 4, WW4 = WW_N / 4;
    int i = blockIdx.x * 256 + threadIdx.x;
    uint2 H, L;
    if (i < FF4) {
        split4(reinterpret_cast<const float4*>(f_f)[i], H, L);
        int idx = i * 4;
        int b   = idx >> 18;        // / (Tt*Fdim)
        int rem = idx & 262143;
        int t   = rem >> 10;        // / Fdim
        int f   = rem & 1023;
        size_t dst = ((size_t)b << 18) + ((size_t)(f >> 4) << 12) + (t << 4) + (f & 15);
        *reinterpret_cast<uint2*>(g_ffH + dst) = H;
        *reinterpret_cast<uint2*>(g_ffL + dst) = L;
    } else if (i < FF4 + WW4) {
        int j = i - FF4;
        split4(reinterpret_cast<const float4*>(W2)[j], H, L);
        reinterpret_cast<uint2*>(g_W2H)[j] = H;
        reinterpret_cast<uint2*>(g_W2L)[j] = L;
    } else {
        int j = i - FF4 - WW4;
        split4(reinterpret_cast<const float4*>(Mw1)[j], H, L);
        reinterpret_cast<uint2*>(g_M1H)[j] = H;
        reinterpret_cast<uint2*>(g_M1L)[j] = L;
    }
}

// ---------------------------------------------------------------------------
// bc[n] = W1[n,:]·bf + b1[n]
// ---------------------------------------------------------------------------
__global__ void bc_kernel(const float* __restrict__ W1, const float* __restrict__ bf,
                          const float* __restrict__ b1) {
    __shared__ float red[128];
    int n = blockIdx.x;
    float s = 0.f;
    for (int j = threadIdx.x; j < Hdim; j += 128)
        s = fmaf(W1[n * Hdim + j], bf[j], s);
    red[threadIdx.x] = s;
    __syncthreads();
    for (int st = 64; st > 0; st >>= 1) {
        if (threadIdx.x < st) red[threadIdx.x] += red[threadIdx.x + st];
        __syncthreads();
    }
    if (threadIdx.x == 0) g_bc[n] = red[0] + b1[n];
}

// ---------------------------------------------------------------------------
// v[j] = Mw3 · Mw2[:,j];  cbias = Mw3·Mb2 + Mb3
// ---------------------------------------------------------------------------
__global__ void vc_kernel(const float* __restrict__ Mw2, const float* __restrict__ Mb2,
                          const float* __restrict__ Mw3, const float* __restrict__ Mb3) {
    int j = blockIdx.x * blockDim.x + threadIdx.x;
    if (j < Hdim) {
        float s = 0.f;
        #pragma unroll
        for (int k = 0; k < 32; k++) s = fmaf(Mw3[k], Mw2[k * Hdim + j], s);
        g_v[j] = s;
    }
    if (j == 0) {
        float c = Mb3[0];
        #pragma unroll
        for (int k = 0; k < 32; k++) c = fmaf(Mw3[k], Mb2[k], c);
        g_cbias = c;
    }
}

// ---------------------------------------------------------------------------
// Wc = W1 @ Wf (fp32, 64x64 tile, 1024 thr, 4-way in-block split-K).
// ---------------------------------------------------------------------------
__global__ __launch_bounds__(1024) void wc_kernel(const float* __restrict__ W1,
                                                  const float* __restrict__ Wf) {
    __shared__ float sm[8704];
    const int tid = threadIdx.x;
    const int g = tid >> 8;
    const int t = tid & 255;
    const int tym = t >> 4, txn = t & 15;
    const int m0 = blockIdx.y * 64, n0 = blockIdx.x * 64;
    float* Asg = sm + g * 2176;
    float* Bsg = Asg + 1088;
    float acc[4][4];
    #pragma unroll
    for (int i = 0; i < 4; i++)
        #pragma unroll
        for (int j = 0; j < 4; j++) acc[i][j] = 0.f;

    const int kbase = g * 128;
    for (int kt = 0; kt < 128; kt += 16) {
        const int k = kbase + kt;
        {
            int r = t >> 2, c = (t & 3) * 4;
            const float4 v = *reinterpret_cast<const float4*>(W1 + (size_t)(m0 + r) * Hdim + k + c);
            Asg[(c + 0) * 68 + r] = v.x; Asg[(c + 1) * 68 + r] = v.y;
            Asg[(c + 2) * 68 + r] = v.z; Asg[(c + 3) * 68 + r] = v.w;
        }
        {
            int kr = t >> 4, cc = (t & 15) * 4;
            const float4 v = *reinterpret_cast<const float4*>(Wf + (size_t)(k + kr) * Fdim + n0 + cc);
            *reinterpret_cast<float4*>(&Bsg[kr * 68 + cc]) = v;
        }
        __syncthreads();
        #pragma unroll
        for (int kk = 0; kk < 16; kk++) {
            float a[4], b[4];
            #pragma unroll
            for (int i = 0; i < 4; i++) a[i] = Asg[kk * 68 + tym * 4 + i];
            #pragma unroll
            for (int j = 0; j < 4; j++) b[j] = Bsg[kk * 68 + txn * 4 + j];
            #pragma unroll
            for (int i = 0; i < 4; i++)
                #pragma unroll
                for (int j = 0; j < 4; j++)
                    acc[i][j] = fmaf(a[i], b[j], acc[i][j]);
        }
        __syncthreads();
    }
    float* part0 = sm;
    float* part1 = sm + 4352;
    __syncthreads();
    if (g == 1 || g == 3) {
        float* p = (g == 1) ? part0 : part1;
        #pragma unroll
        for (int i = 0; i < 4; i++)
            #pragma unroll
            for (int j = 0; j < 4; j++)
                p[(tym * 4 + i) * 68 + txn * 4 + j] = acc[i][j];
    }
    __syncthreads();
    if (g == 0)
        #pragma unroll
        for (int i = 0; i < 4; i++)
            #pragma unroll
            for (int j = 0; j < 4; j++)
                acc[i][j] += part0[(tym * 4 + i) * 68 + txn * 4 + j];
    if (g == 2)
        #pragma unroll
        for (int i = 0; i < 4; i++)
            #pragma unroll
            for (int j = 0; j < 4; j++)
                acc[i][j] += part1[(tym * 4 + i) * 68 + txn * 4 + j];
    __syncthreads();
    if (g == 2) {
        #pragma unroll
        for (int i = 0; i < 4; i++)
            #pragma unroll
            for (int j = 0; j < 4; j++)
                part0[(tym * 4 + i) * 68 + txn * 4 + j] = acc[i][j];
    }
    __syncthreads();
    if (g == 0) {
        #pragma unroll
        for (int i = 0; i < 4; i++)
            #pragma unroll
            for (int j = 0; j < 4; j++) {
                float v = acc[i][j] + part0[(tym * 4 + i) * 68 + txn * 4 + j];
                size_t off = (size_t)(m0 + tym * 4 + i) * Fdim + n0 + txn * 4 + j;
                __nv_bfloat16 h = __float2bfloat16_rn(v);
                g_WcH[off] = h;
                g_WcL[off] = __float2bfloat16_rn(v - __bfloat162float(h));
            }
    }
}

// ---------------------------------------------------------------------------
// Fragment scan + bit-pack
// ---------------------------------------------------------------------------
__device__ __forceinline__ void scan_frags_and_pack(
    float (&acc)[2][8][4], float (*xs)[68],
    int b, int n0, unsigned* __restrict__ bits_out)
{
    const int tid = threadIdx.x;
    const int w = tid >> 5, lane = tid & 31;
    const int q = lane >> 2, cp = 2 * (lane & 3);
    float m = 0.f;
    __syncthreads();
    #pragma unroll
    for (int c = 0; c < 4; c++) {
        if ((w >> 1) == c) {
            const int rb = (w & 1) * 32;
            #pragma unroll
            for (int st = 0; st < 2; st++) {
                #pragma unroll
                for (int ns = 0; ns < 8; ns++) {
                    int r = rb + st * 16 + q;
                    int col = ns * 8 + cp;
                    xs[r][col]         = acc[st][ns][0];
                    xs[r][col + 1]     = acc[st][ns][1];
                    xs[r + 8][col]     = acc[st][ns][2];
                    xs[r + 8][col + 1] = acc[st][ns][3];
                }
            }
        }
        __syncthreads();
        if (w < 2) {
            for (int tt = 0; tt < 64; tt++) {
                float x = xs[tt][w * 32 + lane];
                float r = (m > 1.0f) ? 1.0f : 0.0f;
                m = 0.9f * m + x - r;
                unsigned bits = __ballot_sync(0xffffffffu, m > 1.0f);
                if (lane == 0)
                    bits_out[(size_t)(b * Tt + c * 64 + tt) * WPR + (n0 >> 5) + w] = bits;
            }
        }
        __syncthreads();
    }
}

// ---------------------------------------------------------------------------
// fused1: x1 = f_f[b] @ Wc^T + bc (3-pass), scan -> s1 bits.
// A: coalesced cp.async from chunk-major gmem into warp-private single buffer.
// B: cp.async double-buffered. One block sync per chunk.
// smem: AsH [256][24] @0 (12KB), AsL @12288, BsH[2][64][24] @24576 (6KB),
//       BsL[2][64][24] @30720 (6KB). Total 36KB. xs aliases A.
// ---------------------------------------------------------------------------
__global__ __launch_bounds__(256, 2) void fused_x1_mma() {
    __shared__ __align__(16) char sbuf[36864];
    float (*xs)[68] = reinterpret_cast<float(*)[68]>(sbuf);

    const int tid = threadIdx.x;
    const int w = tid >> 5, lane = tid & 31;
    const int n0 = blockIdx.x * 64;
    const int b  = blockIdx.y;

    float acc[2][8][4];
    #pragma unroll
    for (int st = 0; st < 2; st++)
        #pragma unroll
        for (int ns = 0; ns < 8; ns++)
            #pragma unroll
            for (int i = 0; i < 4; i++) acc[st][ns][i] = 0.f;

    // B cp.async mapping (tid<128 -> hi, else lo); buf stride 3072B
    const int brow = (tid & 127) >> 1, bseg = tid & 1;
    const __nv_bfloat16* gsrcB = ((tid < 128) ? g_WcH : g_WcL)
                                 + (size_t)(n0 + brow) * Fdim + bseg * 8;
    char* bDst = sbuf + 24576 + ((tid < 128) ? 0 : 6144) + brow * 48 + bseg * 16;

    // A cp.async mapping: thread writes its own row (tid), both 16B segs, hi+lo
    const __nv_bfloat16* gsrcAH = g_ffH + ((size_t)b << 18) + tid * 16;
    const __nv_bfloat16* gsrcAL = g_ffL + ((size_t)b << 18) + tid * 16;
    char* aDstH = sbuf + tid * 48;
    char* aDstL = sbuf + 12288 + tid * 48;

    // preload chunk 0 (A + B in one group)
    cp_async16(aDstH,      gsrcAH);
    cp_async16(aDstH + 16, gsrcAH + 8);
    cp_async16(aDstL,      gsrcAL);
    cp_async16(aDstL + 16, gsrcAL + 8);
    cp_async16(bDst, gsrcB);
    CP_COMMIT();

    const unsigned sb = smem_u32(sbuf);
    const unsigned aRow = (w * 32 + (lane & 15)) * 48 + (lane >> 4) * 16;
    const unsigned bRow = (lane & 7) + ((lane >> 4) & 1) * 8;
    const unsigned bKofs = ((lane >> 3) & 1) * 16;

    for (int c = 0; c < Fdim / 16; c++) {
        const int buf = c & 1;
        CP_WAIT0();           // A(c) + B(c) arrived (this thread's groups)
        __syncthreads();      // cross-thread visibility; prior-buf reads done
        if (c + 1 < Fdim / 16) {
            cp_async16(bDst + (buf ^ 1) * 3072, gsrcB + (c + 1) * 16);
            CP_COMMIT();
        }
        // A fragments for chunk c (single buffer, warp-private rows)
        unsigned ah[2][4], al[2][4];
        #pragma unroll
        for (int st = 0; st < 2; st++) {
            ldm4(ah[st][0], ah[st][1], ah[st][2], ah[st][3], sb + aRow + st * 768);
            ldm4(al[st][0], al[st][1], al[st][2], al[st][3], sb + 12288 + aRow + st * 768);
        }
        __syncwarp();         // all lanes finished reading A(c) rows
        if (c + 1 < Fdim / 16) {
            const int kofs = (c + 1) * 4096;   // elements per chunk
            cp_async16(aDstH,      gsrcAH + kofs);
            cp_async16(aDstH + 16, gsrcAH + kofs + 8);
            cp_async16(aDstL,      gsrcAL + kofs);
            cp_async16(aDstL + 16, gsrcAL + kofs + 8);
            CP_COMMIT();
        }
        // B fragments + MMA (3-pass)
        const unsigned bB = sb + 24576 + buf * 3072;
        #pragma unroll
        for (int p = 0; p < 4; p++) {
            unsigned bh[4], bl[4];
            const unsigned rowOfs = (p * 16 + bRow) * 48 + bKofs;
            ldm4(bh[0], bh[1], bh[2], bh[3], bB + rowOfs);
            ldm4(bl[0], bl[1], bl[2], bl[3], bB + 6144 + rowOfs);
            #pragma unroll
            for (int st = 0; st < 2; st++) {
                mma16816(acc[st][2 * p], ah[st][0], ah[st][1], ah[st][2], ah[st][3], bh[0], bh[1]);
                mma16816(acc[st][2 * p], ah[st][0], ah[st][1], ah[st][2], ah[st][3], bl[0], bl[1]);
                mma16816(acc[st][2 * p], al[st][0], al[st][1], al[st][2], al[st][3], bh[0], bh[1]);
                mma16816(acc[st][2 * p + 1], ah[st][0], ah[st][1], ah[st][2], ah[st][3], bh[2], bh[3]);
                mma16816(acc[st][2 * p + 1], ah[st][0], ah[st][1], ah[st][2], ah[st][3], bl[2], bl[3]);
                mma16816(acc[st][2 * p + 1], al[st][0], al[st][1], al[st][2], al[st][3], bh[2], bh[3]);
            }
        }
    }
    {
        const int cp = 2 * (lane & 3);
        #pragma unroll
        for (int ns = 0; ns < 8; ns++) {
            float b0 = g_bc[n0 + ns * 8 + cp];
            float b1 = g_bc[n0 + ns * 8 + cp + 1];
            #pragma unroll
            for (int st = 0; st < 2; st++) {
                acc[st][ns][0] += b0; acc[st][ns][1] += b1;
                acc[st][ns][2] += b0; acc[st][ns][3] += b1;
            }
        }
    }
    scan_frags_and_pack(acc, xs, b, n0, g_s1bits);
}

// ---------------------------------------------------------------------------
// Shared body for fused2 / fusedM: A from spike bits, 32-k chunks, 2-pass B.
// ---------------------------------------------------------------------------
__device__ __forceinline__ void spike_gemm_body(
    char* sbuf, const unsigned* __restrict__ bitsIn,
    const __nv_bfloat16* __restrict__ WH, const __nv_bfloat16* __restrict__ WL,
    int b, int n0, float (&acc)[2][8][4])
{
    const int tid = threadIdx.x;
    const int w = tid >> 5, lane = tid & 31;

    unsigned bDstOff[2];
    const __nv_bfloat16* bSrc[2];
    #pragma unroll
    for (int j = 0; j < 2; j++) {
        int u = tid * 2 + j;
        int hl = u >> 8, r = u & 255;
        int ksub = r >> 7, rr = r & 127;
        int row = rr >> 1, seg = rr & 1;
        bDstOff[j] = 24576 + hl * 12288 + ksub * 3072 + row * 48 + seg * 16;
        bSrc[j] = (hl ? WL : WH) + (size_t)(n0 + row) * Hdim + ksub * 16 + seg * 8;
    }
    unsigned short (*AsH)[256][24] = reinterpret_cast<unsigned short(*)[256][24]>(sbuf);

    cp_async16(sbuf + bDstOff[0], bSrc[0]);
    cp_async16(sbuf + bDstOff[1], bSrc[1]);
    CP_COMMIT();
    unsigned rW = bitsIn[(size_t)(b * Tt + tid) * WPR + 0];

    const unsigned aRowBase = w * 32 + (lane & 15);
    const unsigned aKofs = (lane >> 4) * 16;
    const unsigned bRow = (lane & 7) + ((lane >> 4) & 1) * 8;
    const unsigned bKofs = ((lane >> 3) & 1) * 16;

    for (int c = 0; c < Hdim / 32; c++) {
        const int buf = c & 1;
        #pragma unroll
        for (int ksub = 0; ksub < 2; ksub++) {
            unsigned e[8];
            const unsigned sh = ksub * 16;
            #pragma unroll
            for (int i = 0; i < 8; i++) {
                unsigned q0 = (rW >> (sh + 2 * i)) & 1u;
                unsigned q1 = (rW >> (sh + 2 * i + 1)) & 1u;
                e[i] = ((q1 * 0x3F80u) << 16) | (q0 * 0x3F80u);
            }
            uint4* d = reinterpret_cast<uint4*>(&AsH[ksub][tid][0]);
            d[0] = make_uint4(e[0], e[1], e[2], e[3]);
            d[1] = make_uint4(e[4], e[5], e[6], e[7]);
        }
        if (c + 1 < Hdim / 32)
            rW = bitsIn[(size_t)(b * Tt + tid) * WPR + c + 1];
        CP_WAIT0();
        __syncthreads();
        if (c + 1 < Hdim / 32) {
            const unsigned bufOfs = (buf ^ 1) * 6144;
            cp_async16(sbuf + bDstOff[0] + bufOfs, bSrc[0] + (c + 1) * 32);
            cp_async16(sbuf + bDstOff[1] + bufOfs, bSrc[1] + (c + 1) * 32);
            CP_COMMIT();
        }
        __syncwarp();

        #pragma unroll
        for (int ksub = 0; ksub < 2; ksub++) {
            unsigned ah[2][4];
            #pragma unroll
            for (int st = 0; st < 2; st++)
                ldm4(ah[st][0], ah[st][1], ah[st][2], ah[st][3],
                     smem_u32(&AsH[ksub][aRowBase + st * 16][0]) + aKofs);
            const unsigned bBase = 24576 + buf * 6144 + ksub * 3072;
            #pragma unroll
            for (int p = 0; p < 4; p++) {
                unsigned bh[4], bl[4];
                unsigned rowOfs = (p * 16 + bRow) * 48 + bKofs;
                ldm4(bh[0], bh[1], bh[2], bh[3], smem_u32(sbuf) + bBase + rowOfs);
                ldm4(bl[0], bl[1], bl[2], bl[3], smem_u32(sbuf) + bBase + 12288 + rowOfs);
                #pragma unroll
                for (int st = 0; st < 2; st++) {
                    mma16816(acc[st][2 * p], ah[st][0], ah[st][1], ah[st][2], ah[st][3], bh[0], bh[1]);
                    mma16816(acc[st][2 * p], ah[st][0], ah[st][1], ah[st][2], ah[st][3], bl[0], bl[1]);
                    mma16816(acc[st][2 * p + 1], ah[st][0], ah[st][1], ah[st][2], ah[st][3], bh[2], bh[3]);
                    mma16816(acc[st][2 * p + 1], ah[st][0], ah[st][1], ah[st][2], ah[st][3], bl[2], bl[3]);
                }
            }
        }
    }
}

// ---------------------------------------------------------------------------
// fused2: x2 = s1 @ W2^T + b2, scan -> s2 bits
// ---------------------------------------------------------------------------
__global__ __launch_bounds__(256, 2) void fused_x2_mma(const float* __restrict__ b2) {
    __shared__ __align__(16) char sbuf[49152];
    float (*xs)[68] = reinterpret_cast<float(*)[68]>(sbuf);
    const int lane = threadIdx.x & 31;
    const int n0 = blockIdx.x * 64;
    const int b  = blockIdx.y;

    float acc[2][8][4];
    #pragma unroll
    for (int st = 0; st < 2; st++)
        #pragma unroll
        for (int ns = 0; ns < 8; ns++)
            #pragma unroll
            for (int i = 0; i < 4; i++) acc[st][ns][i] = 0.f;

    spike_gemm_body(sbuf, g_s1bits, g_W2H, g_W2L, b, n0, acc);

    {
        const int cp = 2 * (lane & 3);
        #pragma unroll
        for (int ns = 0; ns < 8; ns++) {
            float b0 = b2[n0 + ns * 8 + cp];
            float b1 = b2[n0 + ns * 8 + cp + 1];
            #pragma unroll
            for (int st = 0; st < 2; st++) {
                acc[st][ns][0] += b0; acc[st][ns][1] += b1;
                acc[st][ns][2] += b0; acc[st][ns][3] += b1;
            }
        }
    }
    scan_frags_and_pack(acc, xs, b, n0, g_s2bits);
}

// ---------------------------------------------------------------------------
// fusedM: relu(s2 @ Mw1^T + Mb1) . v -> per-n-tile logit partials
// ---------------------------------------------------------------------------
__global__ __launch_bounds__(256, 2) void fused_mil_mma(const float* __restrict__ Mb1) {
    __shared__ __align__(16) char sbuf[49152];
    const int tid = threadIdx.x;
    const int w = tid >> 5, lane = tid & 31;
    const int n0 = blockIdx.x * 64;
    const int b  = blockIdx.y;

    float acc[2][8][4];
    #pragma unroll
    for (int st = 0; st < 2; st++)
        #pragma unroll
        for (int ns = 0; ns < 8; ns++)
            #pragma unroll
            for (int i = 0; i < 4; i++) acc[st][ns][i] = 0.f;

    spike_gemm_body(sbuf, g_s2bits, g_M1H, g_M1L, b, n0, acc);

    {
        const int cp = 2 * (lane & 3);
        #pragma unroll
        for (int st = 0; st < 2; st++) {
            float p0 = 0.f, p1 = 0.f;
            #pragma unroll
            for (int ns = 0; ns < 8; ns++) {
                int col = n0 + ns * 8 + cp;
                float bb0 = Mb1[col], bb1 = Mb1[col + 1];
                float vv0 = g_v[col], vv1 = g_v[col + 1];
                float z;
                z = acc[st][ns][0] + bb0; z = z > 0.f ? z : 0.f; p0 = fmaf(z, vv0, p0);
                z = acc[st][ns][1] + bb1; z = z > 0.f ? z : 0.f; p0 = fmaf(z, vv1, p0);
                z = acc[st][ns][2] + bb0; z = z > 0.f ? z : 0.f; p1 = fmaf(z, vv0, p1);
                z = acc[st][ns][3] + bb1; z = z > 0.f ? z : 0.f; p1 = fmaf(z, vv1, p1);
            }
            p0 += __shfl_down_sync(0xffffffffu, p0, 2, 4);
            p0 += __shfl_down_sync(0xffffffffu, p0, 1, 4);
            p1 += __shfl_down_sync(0xffffffffu, p1, 2, 4);
            p1 += __shfl_down_sync(0xffffffffu, p1, 1, 4);
            if ((lane & 3) == 0) {
                int row = w * 32 + st * 16 + (lane >> 2);
                g_logitParts[(size_t)blockIdx.x * BT + b * Tt + row] = p0;
                g_logitParts[(size_t)blockIdx.x * BT + b * Tt + row + 8] = p1;
            }
        }
    }
}

// ---------------------------------------------------------------------------
// Per batch: sigmoid + top-17 mean.
// ---------------------------------------------------------------------------
__global__ void topk_kernel(float* __restrict__ out) {
    __shared__ float vals[Tt];
    __shared__ float rv[Tt];
    __shared__ int   ri[Tt];
    int b = blockIdx.x, t = threadIdx.x;
    float pre = g_cbias;
    #pragma unroll
    for (int z = 0; z < 8; z++) pre += g_logitParts[(size_t)z * BT + b * Tt + t];
    vals[t] = 1.0f / (1.0f + expf(-pre));
    __syncthreads();
    float sum = 0.f;
    for (int it = 0; it < TOPK; it++) {
        rv[t] = vals[t]; ri[t] = t;
        __syncthreads();
        for (int st = Tt / 2; st > 0; st >>= 1) {
            if (t < st && rv[t + st] > rv[t]) { rv[t] = rv[t + st]; ri[t] = ri[t + st]; }
            __syncthreads();
        }
        if (t == 0) { sum += rv[0]; vals[ri[0]] = -FLT_MAX; }
        __syncthreads();
    }
    if (t == 0) out[b] = sum / (float)TOPK;
}

// ---------------------------------------------------------------------------
namespace {
struct EnvSetup {
    EnvSetup() { setenv("CUDA_MODULE_LOADING", "EAGER", 1); }
};
EnvSetup g_env_setup;
}

// ---------------------------------------------------------------------------
extern "C" void kernel_launch(void* const* d_in, const int* in_sizes, int n_in,
                              void* d_out, int out_size) {
    (void)in_sizes; (void)n_in; (void)out_size;
    const float* f_f = (const float*)d_in[0];
    const float* Wf  = (const float*)d_in[2];
    const float* bf  = (const float*)d_in[3];
    const float* W1  = (const float*)d_in[4];
    const float* b1  = (const float*)d_in[5];
    const float* W2  = (const float*)d_in[6];
    const float* b2  = (const float*)d_in[7];
    const float* Mw1 = (const float*)d_in[8];
    const float* Mb1 = (const float*)d_in[9];
    const float* Mw2 = (const float*)d_in[10];
    const float* Mb2 = (const float*)d_in[11];
    const float* Mw3 = (const float*)d_in[12];
    const float* Mb3 = (const float*)d_in[13];
    float* out = (float*)d_out;

    prep_split_kernel<<<(FF_N / 4 + 2 * (WW_N / 4)) / 256, 256>>>(f_f, W2, Mw1);   // 0
    bc_kernel<<<Hdim, 128>>>(W1, bf, b1);                                           // 1
    wc_kernel<<<dim3(Fdim / 64, Hdim / 64), 1024>>>(W1, Wf);                        // 2
    fused_x1_mma<<<dim3(Hdim / 64, Bb), 256>>>();                                   // 3 <- profiled
    vc_kernel<<<2, 256>>>(Mw2, Mb2, Mw3, Mb3);                                      // 4
    fused_x2_mma<<<dim3(Hdim / 64, Bb), 256>>>(b2);                                 // 5
    fused_mil_mma<<<dim3(Hdim / 64, Bb), 256>>>(Mb1);                               // 6
    topk_kernel<<<Bb, Tt>>>(out);                                                   // 7
}